// round 12
// baseline (speedup 1.0000x reference)
#include <cuda_runtime.h>
#include <cuda_bf16.h>
#include <cstdint>

// RoIAlign: feat [4,256,100,100] f32, rois [512,5] f32 -> out [512,256,7,7] f32
// SPATIAL_SCALE=0.25, SAMPLING_RATIO=2, ALIGNED=true, OUT 7x7.
//
// Warp-pair pipelines, double-buffered cp.async (R10 structure); taps as
// absolute smem addresses (buffer 0) + +2800 immediate for buffer 1 ->
// zero-ALU inner loop. __launch_bounds__(256,5) caps regs at 51 so 5 CTAs
// (40 warps) fit per SM. 4 pairs/block, 32 channels/block, grid (512,8).

#define FH 100
#define FW 100
#define FC 256
#define OUTHW 49
#define RROWS 25          // max region rows
#define RSTRIDE 28        // region row stride in floats (mult of 4)
#define PAIRS 4           // warp pairs per block
#define CSPLIT 8          // channel-split blocks per RoI
#define CPB (FC / CSPLIT) // 32 channels per block
#define CPP (CPB / PAIRS) // 8 channels per pair
#define BUFB (RROWS * RSTRIDE * 4)  // 2800 bytes per buffer

#define CP_COMMIT asm volatile("cp.async.commit_group;\n" ::)
#define CP_WAIT(n) asm volatile("cp.async.wait_group %0;\n" :: "n"(n))
#define BAR64(id) asm volatile("bar.sync %0, 64;\n" :: "r"(id) : "memory")

__device__ __forceinline__ void cp16(uint32_t saddr, const float* g) {
    asm volatile("cp.async.cg.shared.global [%0], [%1], 16;\n" :: "r"(saddr), "l"(g));
}
__device__ __forceinline__ float lds0(uint32_t a) {
    float v; asm volatile("ld.shared.f32 %0, [%1];" : "=f"(v) : "r"(a)); return v;
}
__device__ __forceinline__ float lds1(uint32_t a) {
    float v; asm volatile("ld.shared.f32 %0, [%1+2800];" : "=f"(v) : "r"(a)); return v;
}

__global__ __launch_bounds__(256, 5) void roialign_kernel(
    const float* __restrict__ feat,
    const float* __restrict__ rois,
    float* __restrict__ out)
{
    __shared__ float s_reg[PAIRS][2][RROWS * RSTRIDE];  // 22400 B

    const int k      = blockIdx.x;
    const int cbase  = blockIdx.y * CPB;
    const int tid    = threadIdx.x;
    const int wid    = tid >> 5;
    const int lane   = tid & 31;
    const int pair   = wid >> 1;
    const int lane64 = ((wid & 1) << 5) + lane;   // 0..63 within pair

    // --- RoI params (broadcast) ---
    const int   b  = (int)__ldg(rois + k * 5 + 0);
    const float x1 = __ldg(rois + k * 5 + 1);
    const float y1 = __ldg(rois + k * 5 + 2);
    const float x2 = __ldg(rois + k * 5 + 3);
    const float y2 = __ldg(rois + k * 5 + 4);

    const float sw = x1 * 0.25f - 0.5f;
    const float sh = y1 * 0.25f - 0.5f;
    const float bw = (x2 * 0.25f - 0.5f - sw) * (1.0f / 7.0f);
    const float bh = (y2 * 0.25f - 0.5f - sh) * (1.0f / 7.0f);

    // --- region bounds (samples monotone in ph/pw) ---
    float ya = fmaxf(sh + 0.25f * bh, 0.0f);
    int   y0 = (int)ya;          if (y0 >= FH - 1) y0 = FH - 1;
    float yb = fmaxf(sh + 6.75f * bh, 0.0f);
    int   yle = (int)yb;
    int   y1i = (yle >= FH - 1) ? (FH - 1) : (yle + 1);
    int   h = y1i - y0 + 1;      if (h > RROWS) h = RROWS;

    float xa = fmaxf(sw + 0.25f * bw, 0.0f);
    int   x0 = (int)xa;          if (x0 >= FW - 1) x0 = FW - 1;
    float xb = fmaxf(sw + 6.75f * bw, 0.0f);
    int   xle = (int)xb;
    int   x1i = (xle >= FW - 1) ? (FW - 1) : (xle + 1);

    const int x0a  = x0 & ~3;                 // 16B-aligned region start
    int       wext = x1i - x0a + 1;
    if (wext > RSTRIDE) wext = RSTRIDE;
    const int w4   = (wext + 3) >> 2;         // 16B chunks per row (<=7)

    const uint32_t s0 = (uint32_t)__cvta_generic_to_shared(&s_reg[pair][0][0]);

    // --- taps as absolute smem addresses into buffer 0 ---
    uint32_t a16[16];
    float    wy[4], wx[4];
    const int  p      = lane64;
    const bool active = (p < OUTHW);

    if (active) {
        const int ph = p / 7;
        const int pw = p - ph * 7;
        int yoff[4], xoff[4];

        #pragma unroll
        for (int i = 0; i < 2; i++) {
            float y = sh + (float)ph * bh + ((float)i + 0.5f) * (bh * 0.5f);
            y = fmaxf(y, 0.0f);
            int yl = (int)y;
            int yh = (yl >= FH - 1) ? (FH - 1) : (yl + 1);
            yl     = (yl >= FH - 1) ? (FH - 1) : yl;
            float ly = y - (float)yl;
            yoff[2 * i + 0] = (yl - y0) * RSTRIDE;  wy[2 * i + 0] = 0.25f * (1.0f - ly);
            yoff[2 * i + 1] = (yh - y0) * RSTRIDE;  wy[2 * i + 1] = 0.25f * ly;

            float x = sw + (float)pw * bw + ((float)i + 0.5f) * (bw * 0.5f);
            x = fmaxf(x, 0.0f);
            int xl = (int)x;
            int xh = (xl >= FW - 1) ? (FW - 1) : (xl + 1);
            xl     = (xl >= FW - 1) ? (FW - 1) : xl;
            float lx = x - (float)xl;
            xoff[2 * i + 0] = xl - x0a;  wx[2 * i + 0] = 1.0f - lx;
            xoff[2 * i + 1] = xh - x0a;  wx[2 * i + 1] = lx;
        }

        #pragma unroll
        for (int r4 = 0; r4 < 4; r4++)
            #pragma unroll
            for (int cx = 0; cx < 4; cx++)
                a16[r4 * 4 + cx] = s0 + (uint32_t)((yoff[r4] + xoff[cx]) << 2);
    }

    const float* fb = feat + (size_t)b * (FC * FH * FW)
                           + (size_t)cbase * (FH * FW) + y0 * FW + x0a;
    float*       ob = out  + (size_t)k * (FC * OUTHW) + cbase * OUTHW;

    // staging lane mapping: flatten (row, 16B-chunk) over 64 lanes
    const int r_init = lane64 / w4;
    const int c_init = lane64 - r_init * w4;
    const int q64    = 64 / w4;
    const int rem64  = 64 - q64 * w4;

    // channel i of this pair = cbase + pair + PAIRS*i
    auto stage = [&](int i) {
        const float* g = fb + (size_t)(pair + PAIRS * i) * (FH * FW);
        const uint32_t sb = s0 + (uint32_t)(i & 1) * BUFB;
        int r = r_init, c = c_init;
        #pragma unroll
        for (int it = 0; it < 3; it++) {
            if (r < h)
                cp16(sb + (r * (RSTRIDE * 4) + (c << 4)), g + r * FW + (c << 2));
            c += rem64;
            int carry = (c >= w4);
            r += q64 + carry;
            if (carry) c -= w4;
        }
        CP_COMMIT;
    };

    stage(0);
    stage(1);

    const int barid = pair + 1;   // named barriers 1..4 (0 reserved)

    #pragma unroll
    for (int i = 0; i < CPP; i++) {
        if (i < CPP - 1) { CP_WAIT(1); } else { CP_WAIT(0); }
        BAR64(barid);     // channel i's cp.async visible to both warps

        if (active) {
            float acc = 0.0f;
            if ((i & 1) == 0) {           // buffer 0 (i literal after unroll)
                #pragma unroll
                for (int r4 = 0; r4 < 4; r4++) {
                    float rs;
                    rs = wx[0] * lds0(a16[r4 * 4 + 0]);
                    rs = fmaf(wx[1], lds0(a16[r4 * 4 + 1]), rs);
                    rs = fmaf(wx[2], lds0(a16[r4 * 4 + 2]), rs);
                    rs = fmaf(wx[3], lds0(a16[r4 * 4 + 3]), rs);
                    acc = fmaf(wy[r4], rs, acc);
                }
            } else {                      // buffer 1 via +2800 immediate
                #pragma unroll
                for (int r4 = 0; r4 < 4; r4++) {
                    float rs;
                    rs = wx[0] * lds1(a16[r4 * 4 + 0]);
                    rs = fmaf(wx[1], lds1(a16[r4 * 4 + 1]), rs);
                    rs = fmaf(wx[2], lds1(a16[r4 * 4 + 2]), rs);
                    rs = fmaf(wx[3], lds1(a16[r4 * 4 + 3]), rs);
                    acc = fmaf(wy[r4], rs, acc);
                }
            }
            ob[(pair + PAIRS * i) * OUTHW + p] = acc;
        }

        if (i + 2 < CPP) {
            BAR64(barid); // both warps done reading buf (i&1) before restaging
            stage(i + 2);
        }
    }
}

extern "C" void kernel_launch(void* const* d_in, const int* in_sizes, int n_in,
                              void* d_out, int out_size)
{
    const float* feat = (const float*)d_in[0];
    const float* rois = (const float*)d_in[1];
    float*       out  = (float*)d_out;

    cudaFuncSetAttribute(roialign_kernel,
                         cudaFuncAttributePreferredSharedMemoryCarveout, 100);

    const int K = in_sizes[1] / 5;  // 512
    dim3 grid(K, CSPLIT);
    roialign_kernel<<<grid, 256>>>(feat, rois, out);
}

// round 13
// speedup vs baseline: 1.0130x; 1.0130x over previous
#include <cuda_runtime.h>
#include <cuda_bf16.h>
#include <cstdint>

// RoIAlign: feat [4,256,100,100] f32, rois [512,5] f32 -> out [512,256,7,7] f32
// SPATIAL_SCALE=0.25, SAMPLING_RATIO=2, ALIGNED=true, OUT 7x7.
//
// Warp-pair pipelines, double-buffered cp.async; taps as absolute smem
// addresses (buffer 0) + +2800 immediate for buffer 1 -> zero-ALU inner loop.
// CSPLIT=4: 64 channels/block (16 per pair), prologue amortized 2x vs R10;
// stage(0)/stage(1) issued BEFORE tap computation so the tap chain overlaps
// the first cp.async flight. 4 pairs/block, grid (512,4), (256,4).

#define FH 100
#define FW 100
#define FC 256
#define OUTHW 49
#define RROWS 25          // max region rows
#define RSTRIDE 28        // region row stride in floats (mult of 4)
#define PAIRS 4           // warp pairs per block
#define CSPLIT 4          // channel-split blocks per RoI
#define CPB (FC / CSPLIT) // 64 channels per block
#define CPP (CPB / PAIRS) // 16 channels per pair
#define BUFB (RROWS * RSTRIDE * 4)  // 2800 bytes per buffer

#define CP_COMMIT asm volatile("cp.async.commit_group;\n" ::)
#define CP_WAIT(n) asm volatile("cp.async.wait_group %0;\n" :: "n"(n))
#define BAR64(id) asm volatile("bar.sync %0, 64;\n" :: "r"(id) : "memory")

__device__ __forceinline__ void cp16(uint32_t saddr, const float* g) {
    asm volatile("cp.async.cg.shared.global [%0], [%1], 16;\n" :: "r"(saddr), "l"(g));
}
__device__ __forceinline__ float lds0(uint32_t a) {
    float v; asm volatile("ld.shared.f32 %0, [%1];" : "=f"(v) : "r"(a)); return v;
}
__device__ __forceinline__ float lds1(uint32_t a) {
    float v; asm volatile("ld.shared.f32 %0, [%1+2800];" : "=f"(v) : "r"(a)); return v;
}

__global__ __launch_bounds__(256, 4) void roialign_kernel(
    const float* __restrict__ feat,
    const float* __restrict__ rois,
    float* __restrict__ out)
{
    __shared__ float s_reg[PAIRS][2][RROWS * RSTRIDE];  // 22400 B

    const int k      = blockIdx.x;
    const int cbase  = blockIdx.y * CPB;
    const int tid    = threadIdx.x;
    const int wid    = tid >> 5;
    const int lane   = tid & 31;
    const int pair   = wid >> 1;
    const int lane64 = ((wid & 1) << 5) + lane;   // 0..63 within pair

    // --- RoI params (broadcast) ---
    const int   b  = (int)__ldg(rois + k * 5 + 0);
    const float x1 = __ldg(rois + k * 5 + 1);
    const float y1 = __ldg(rois + k * 5 + 2);
    const float x2 = __ldg(rois + k * 5 + 3);
    const float y2 = __ldg(rois + k * 5 + 4);

    const float sw = x1 * 0.25f - 0.5f;
    const float sh = y1 * 0.25f - 0.5f;
    const float bw = (x2 * 0.25f - 0.5f - sw) * (1.0f / 7.0f);
    const float bh = (y2 * 0.25f - 0.5f - sh) * (1.0f / 7.0f);

    // --- region bounds (samples monotone in ph/pw) ---
    float ya = fmaxf(sh + 0.25f * bh, 0.0f);
    int   y0 = (int)ya;          if (y0 >= FH - 1) y0 = FH - 1;
    float yb = fmaxf(sh + 6.75f * bh, 0.0f);
    int   yle = (int)yb;
    int   y1i = (yle >= FH - 1) ? (FH - 1) : (yle + 1);
    int   h = y1i - y0 + 1;      if (h > RROWS) h = RROWS;

    float xa = fmaxf(sw + 0.25f * bw, 0.0f);
    int   x0 = (int)xa;          if (x0 >= FW - 1) x0 = FW - 1;
    float xb = fmaxf(sw + 6.75f * bw, 0.0f);
    int   xle = (int)xb;
    int   x1i = (xle >= FW - 1) ? (FW - 1) : (xle + 1);

    const int x0a  = x0 & ~3;                 // 16B-aligned region start
    int       wext = x1i - x0a + 1;
    if (wext > RSTRIDE) wext = RSTRIDE;
    const int w4   = (wext + 3) >> 2;         // 16B chunks per row (<=7)

    const uint32_t s0 = (uint32_t)__cvta_generic_to_shared(&s_reg[pair][0][0]);

    const float* fb = feat + (size_t)b * (FC * FH * FW)
                           + (size_t)cbase * (FH * FW) + y0 * FW + x0a;
    float*       ob = out  + (size_t)k * (FC * OUTHW) + cbase * OUTHW;

    // staging lane mapping: flatten (row, 16B-chunk) over 64 lanes
    const int r_init = lane64 / w4;
    const int c_init = lane64 - r_init * w4;
    const int q64    = 64 / w4;
    const int rem64  = 64 - q64 * w4;

    // channel i of this pair = cbase + pair + PAIRS*i
    auto stage = [&](int i) {
        const float* g = fb + (size_t)(pair + PAIRS * i) * (FH * FW);
        const uint32_t sb = s0 + (uint32_t)(i & 1) * BUFB;
        int r = r_init, c = c_init;
        #pragma unroll
        for (int it = 0; it < 3; it++) {
            if (r < h)
                cp16(sb + (r * (RSTRIDE * 4) + (c << 4)), g + r * FW + (c << 2));
            c += rem64;
            int carry = (c >= w4);
            r += q64 + carry;
            if (carry) c -= w4;
        }
        CP_COMMIT;
    };

    // issue first two stages BEFORE computing taps: tap math overlaps flight
    stage(0);
    stage(1);

    // --- taps as absolute smem addresses into buffer 0 ---
    uint32_t a16[16];
    float    wy[4], wx[4];
    const int  p      = lane64;
    const bool active = (p < OUTHW);

    if (active) {
        const int ph = p / 7;
        const int pw = p - ph * 7;
        int yoff[4], xoff[4];

        #pragma unroll
        for (int i = 0; i < 2; i++) {
            float y = sh + (float)ph * bh + ((float)i + 0.5f) * (bh * 0.5f);
            y = fmaxf(y, 0.0f);
            int yl = (int)y;
            int yh = (yl >= FH - 1) ? (FH - 1) : (yl + 1);
            yl     = (yl >= FH - 1) ? (FH - 1) : yl;
            float ly = y - (float)yl;
            yoff[2 * i + 0] = (yl - y0) * RSTRIDE;  wy[2 * i + 0] = 0.25f * (1.0f - ly);
            yoff[2 * i + 1] = (yh - y0) * RSTRIDE;  wy[2 * i + 1] = 0.25f * ly;

            float x = sw + (float)pw * bw + ((float)i + 0.5f) * (bw * 0.5f);
            x = fmaxf(x, 0.0f);
            int xl = (int)x;
            int xh = (xl >= FW - 1) ? (FW - 1) : (xl + 1);
            xl     = (xl >= FW - 1) ? (FW - 1) : xl;
            float lx = x - (float)xl;
            xoff[2 * i + 0] = xl - x0a;  wx[2 * i + 0] = 1.0f - lx;
            xoff[2 * i + 1] = xh - x0a;  wx[2 * i + 1] = lx;
        }

        #pragma unroll
        for (int r4 = 0; r4 < 4; r4++)
            #pragma unroll
            for (int cx = 0; cx < 4; cx++)
                a16[r4 * 4 + cx] = s0 + (uint32_t)((yoff[r4] + xoff[cx]) << 2);
    }

    const int barid = pair + 1;   // named barriers 1..4 (0 reserved)

    #pragma unroll
    for (int i = 0; i < CPP; i++) {
        if (i < CPP - 1) { CP_WAIT(1); } else { CP_WAIT(0); }
        BAR64(barid);     // channel i's cp.async visible to both warps

        if (active) {
            float acc = 0.0f;
            if ((i & 1) == 0) {           // buffer 0 (i literal after unroll)
                #pragma unroll
                for (int r4 = 0; r4 < 4; r4++) {
                    float rs;
                    rs = wx[0] * lds0(a16[r4 * 4 + 0]);
                    rs = fmaf(wx[1], lds0(a16[r4 * 4 + 1]), rs);
                    rs = fmaf(wx[2], lds0(a16[r4 * 4 + 2]), rs);
                    rs = fmaf(wx[3], lds0(a16[r4 * 4 + 3]), rs);
                    acc = fmaf(wy[r4], rs, acc);
                }
            } else {                      // buffer 1 via +2800 immediate
                #pragma unroll
                for (int r4 = 0; r4 < 4; r4++) {
                    float rs;
                    rs = wx[0] * lds1(a16[r4 * 4 + 0]);
                    rs = fmaf(wx[1], lds1(a16[r4 * 4 + 1]), rs);
                    rs = fmaf(wx[2], lds1(a16[r4 * 4 + 2]), rs);
                    rs = fmaf(wx[3], lds1(a16[r4 * 4 + 3]), rs);
                    acc = fmaf(wy[r4], rs, acc);
                }
            }
            ob[(pair + PAIRS * i) * OUTHW + p] = acc;
        }

        if (i + 2 < CPP) {
            BAR64(barid); // both warps done reading buf (i&1) before restaging
            stage(i + 2);
        }
    }
}

extern "C" void kernel_launch(void* const* d_in, const int* in_sizes, int n_in,
                              void* d_out, int out_size)
{
    const float* feat = (const float*)d_in[0];
    const float* rois = (const float*)d_in[1];
    float*       out  = (float*)d_out;

    cudaFuncSetAttribute(roialign_kernel,
                         cudaFuncAttributePreferredSharedMemoryCarveout, 100);

    const int K = in_sizes[1] / 5;  // 512
    dim3 grid(K, CSPLIT);
    roialign_kernel<<<grid, 256>>>(feat, rois, out);
}

// round 14
// speedup vs baseline: 1.0477x; 1.0343x over previous
#include <cuda_runtime.h>
#include <cuda_bf16.h>
#include <cstdint>

// RoIAlign: feat [4,256,100,100] f32, rois [512,5] f32 -> out [512,256,7,7] f32
// SPATIAL_SCALE=0.25, SAMPLING_RATIO=2, ALIGNED=true, OUT 7x7.
//
// R10 structure (warp-pair pipelines, double-buffered cp.async, zero-ALU
// inner loop) + XOR-swizzled region layout: row stride 32 floats (128B),
// 16B chunk index XORed with (row&7) -> cross-row taps hit distinct banks.
// Swizzle baked into precomputed absolute tap addresses (free in the loop).
// 4 pairs/block, 32 channels/block, grid (512,8), (256,4).

#define FH 100
#define FW 100
#define FC 256
#define OUTHW 49
#define RROWS 25          // max region rows
#define RSTRIDE 32        // region row stride in floats (128B, 8 chunks)
#define PAIRS 4           // warp pairs per block
#define CSPLIT 8          // channel-split blocks per RoI
#define CPB (FC / CSPLIT) // 32 channels per block
#define CPP (CPB / PAIRS) // 8 channels per pair
#define BUFB (RROWS * RSTRIDE * 4)  // 3200 bytes per buffer

#define CP_COMMIT asm volatile("cp.async.commit_group;\n" ::)
#define CP_WAIT(n) asm volatile("cp.async.wait_group %0;\n" :: "n"(n))
#define BAR64(id) asm volatile("bar.sync %0, 64;\n" :: "r"(id) : "memory")

__device__ __forceinline__ void cp16(uint32_t saddr, const float* g) {
    asm volatile("cp.async.cg.shared.global [%0], [%1], 16;\n" :: "r"(saddr), "l"(g));
}
__device__ __forceinline__ float lds0(uint32_t a) {
    float v; asm volatile("ld.shared.f32 %0, [%1];" : "=f"(v) : "r"(a)); return v;
}
__device__ __forceinline__ float lds1(uint32_t a) {
    float v; asm volatile("ld.shared.f32 %0, [%1+3200];" : "=f"(v) : "r"(a)); return v;
}

__global__ __launch_bounds__(256, 4) void roialign_kernel(
    const float* __restrict__ feat,
    const float* __restrict__ rois,
    float* __restrict__ out)
{
    __shared__ float s_reg[PAIRS][2][RROWS * RSTRIDE];  // 25600 B

    const int k      = blockIdx.x;
    const int cbase  = blockIdx.y * CPB;
    const int tid    = threadIdx.x;
    const int wid    = tid >> 5;
    const int lane   = tid & 31;
    const int pair   = wid >> 1;
    const int lane64 = ((wid & 1) << 5) + lane;   // 0..63 within pair

    // --- RoI params (broadcast) ---
    const int   b  = (int)__ldg(rois + k * 5 + 0);
    const float x1 = __ldg(rois + k * 5 + 1);
    const float y1 = __ldg(rois + k * 5 + 2);
    const float x2 = __ldg(rois + k * 5 + 3);
    const float y2 = __ldg(rois + k * 5 + 4);

    const float sw = x1 * 0.25f - 0.5f;
    const float sh = y1 * 0.25f - 0.5f;
    const float bw = (x2 * 0.25f - 0.5f - sw) * (1.0f / 7.0f);
    const float bh = (y2 * 0.25f - 0.5f - sh) * (1.0f / 7.0f);

    // --- region bounds (samples monotone in ph/pw) ---
    float ya = fmaxf(sh + 0.25f * bh, 0.0f);
    int   y0 = (int)ya;          if (y0 >= FH - 1) y0 = FH - 1;
    float yb = fmaxf(sh + 6.75f * bh, 0.0f);
    int   yle = (int)yb;
    int   y1i = (yle >= FH - 1) ? (FH - 1) : (yle + 1);
    int   h = y1i - y0 + 1;      if (h > RROWS) h = RROWS;

    float xa = fmaxf(sw + 0.25f * bw, 0.0f);
    int   x0 = (int)xa;          if (x0 >= FW - 1) x0 = FW - 1;
    float xb = fmaxf(sw + 6.75f * bw, 0.0f);
    int   xle = (int)xb;
    int   x1i = (xle >= FW - 1) ? (FW - 1) : (xle + 1);

    const int x0a  = x0 & ~3;                 // 16B-aligned region start
    int       wext = x1i - x0a + 1;
    if (wext > 28) wext = 28;                 // data cols <= 28 (region <=25 + align <=3)
    const int w4   = (wext + 3) >> 2;         // 16B chunks per row (<=7)

    const uint32_t s0 = (uint32_t)__cvta_generic_to_shared(&s_reg[pair][0][0]);

    const float* fb = feat + (size_t)b * (FC * FH * FW)
                           + (size_t)cbase * (FH * FW) + y0 * FW + x0a;
    float*       ob = out  + (size_t)k * (FC * OUTHW) + cbase * OUTHW;

    // staging lane mapping: flatten (row, 16B-chunk) over 64 lanes
    const int r_init = lane64 / w4;
    const int c_init = lane64 - r_init * w4;
    const int q64    = 64 / w4;
    const int rem64  = 64 - q64 * w4;

    // channel i of this pair = cbase + pair + PAIRS*i
    // XOR swizzle: data chunk c of row r stored at chunk (c ^ (r&7))
    auto stage = [&](int i) {
        const float* g = fb + (size_t)(pair + PAIRS * i) * (FH * FW);
        const uint32_t sb = s0 + (uint32_t)(i & 1) * BUFB;
        int r = r_init, c = c_init;
        #pragma unroll
        for (int it = 0; it < 3; it++) {
            if (r < h)
                cp16(sb + (uint32_t)(r * 128 + ((c ^ (r & 7)) << 4)),
                     g + r * FW + (c << 2));
            c += rem64;
            int carry = (c >= w4);
            r += q64 + carry;
            if (carry) c -= w4;
        }
        CP_COMMIT;
    };

    // issue first two stages before tap math so it overlaps the flight
    stage(0);
    stage(1);

    // --- taps as absolute (swizzled) smem addresses into buffer 0 ---
    uint32_t a16[16];
    float    wy[4], wx[4];
    const int  p      = lane64;
    const bool active = (p < OUTHW);

    if (active) {
        const int ph = p / 7;
        const int pw = p - ph * 7;
        int yrow[4], xoff[4];

        #pragma unroll
        for (int i = 0; i < 2; i++) {
            float y = sh + (float)ph * bh + ((float)i + 0.5f) * (bh * 0.5f);
            y = fmaxf(y, 0.0f);
            int yl = (int)y;
            int yh = (yl >= FH - 1) ? (FH - 1) : (yl + 1);
            yl     = (yl >= FH - 1) ? (FH - 1) : yl;
            float ly = y - (float)yl;
            yrow[2 * i + 0] = yl - y0;  wy[2 * i + 0] = 0.25f * (1.0f - ly);
            yrow[2 * i + 1] = yh - y0;  wy[2 * i + 1] = 0.25f * ly;

            float x = sw + (float)pw * bw + ((float)i + 0.5f) * (bw * 0.5f);
            x = fmaxf(x, 0.0f);
            int xl = (int)x;
            int xh = (xl >= FW - 1) ? (FW - 1) : (xl + 1);
            xl     = (xl >= FW - 1) ? (FW - 1) : xl;
            float lx = x - (float)xl;
            xoff[2 * i + 0] = xl - x0a;  wx[2 * i + 0] = 1.0f - lx;
            xoff[2 * i + 1] = xh - x0a;  wx[2 * i + 1] = lx;
        }

        #pragma unroll
        for (int r4 = 0; r4 < 4; r4++) {
            const uint32_t rowbase = (uint32_t)(yrow[r4] * 128);
            const uint32_t swz     = (uint32_t)((yrow[r4] & 7) << 4);
            #pragma unroll
            for (int cx = 0; cx < 4; cx++)
                a16[r4 * 4 + cx] = s0 + (rowbase + (((uint32_t)(xoff[cx] << 2)) ^ swz));
        }
    }

    const int barid = pair + 1;   // named barriers 1..4 (0 reserved)

    #pragma unroll
    for (int i = 0; i < CPP; i++) {
        if (i < CPP - 1) { CP_WAIT(1); } else { CP_WAIT(0); }
        BAR64(barid);     // channel i's cp.async visible to both warps

        if (active) {
            float acc = 0.0f;
            if ((i & 1) == 0) {           // buffer 0 (i literal after unroll)
                #pragma unroll
                for (int r4 = 0; r4 < 4; r4++) {
                    float rs;
                    rs = wx[0] * lds0(a16[r4 * 4 + 0]);
                    rs = fmaf(wx[1], lds0(a16[r4 * 4 + 1]), rs);
                    rs = fmaf(wx[2], lds0(a16[r4 * 4 + 2]), rs);
                    rs = fmaf(wx[3], lds0(a16[r4 * 4 + 3]), rs);
                    acc = fmaf(wy[r4], rs, acc);
                }
            } else {                      // buffer 1 via +3200 immediate
                #pragma unroll
                for (int r4 = 0; r4 < 4; r4++) {
                    float rs;
                    rs = wx[0] * lds1(a16[r4 * 4 + 0]);
                    rs = fmaf(wx[1], lds1(a16[r4 * 4 + 1]), rs);
                    rs = fmaf(wx[2], lds1(a16[r4 * 4 + 2]), rs);
                    rs = fmaf(wx[3], lds1(a16[r4 * 4 + 3]), rs);
                    acc = fmaf(wy[r4], rs, acc);
                }
            }
            ob[(pair + PAIRS * i) * OUTHW + p] = acc;
        }

        if (i + 2 < CPP) {
            BAR64(barid); // both warps done reading buf (i&1) before restaging
            stage(i + 2);
        }
    }
}

extern "C" void kernel_launch(void* const* d_in, const int* in_sizes, int n_in,
                              void* d_out, int out_size)
{
    const float* feat = (const float*)d_in[0];
    const float* rois = (const float*)d_in[1];
    float*       out  = (float*)d_out;

    cudaFuncSetAttribute(roialign_kernel,
                         cudaFuncAttributePreferredSharedMemoryCarveout, 100);

    const int K = in_sizes[1] / 5;  // 512
    dim3 grid(K, CSPLIT);
    roialign_kernel<<<grid, 256>>>(feat, rois, out);
}